// round 5
// baseline (speedup 1.0000x reference)
#include <cuda_runtime.h>
#include <math.h>

#define B_  2
#define S_  2048
#define DM_ 1024
#define H_  16
#define D_  64

// Scratch (allowed: __device__ globals). Layout [B, H, S, D].
__device__ float g_q[B_*H_*S_*D_];
__device__ float g_k[B_*H_*S_*D_];
__device__ float g_v[B_*H_*S_*D_];

// ---------------------------------------------------------------------------
// Kernel 1: P[m,n] = sum_k X[m,k] * W[n,k]   (X: [4096,1024], W: [1024,1024])
// 128x128x8 tile, 256 threads, 8x8 microtile. Output written in [B,H,S,D].
// ---------------------------------------------------------------------------
__global__ __launch_bounds__(256)
void qkv_gemm(const float* __restrict__ X,
              const float* __restrict__ Wq,
              const float* __restrict__ Wk,
              const float* __restrict__ Wv)
{
    __shared__ float As[8][128];   // [k][m]
    __shared__ float Bs[8][128];   // [k][n]

    const float* W;
    float* out;
    if (blockIdx.z == 0)      { W = Wq; out = g_q; }
    else if (blockIdx.z == 1) { W = Wk; out = g_k; }
    else                      { W = Wv; out = g_v; }

    const int tid = threadIdx.x;
    const int m0  = blockIdx.y * 128;
    const int n0  = blockIdx.x * 128;
    const int lr  = tid >> 1;          // 0..127
    const int lc  = (tid & 1) * 4;     // 0 or 4
    const float* Ap = X + (size_t)(m0 + lr) * DM_ + lc;
    const float* Bp = W + (size_t)(n0 + lr) * DM_ + lc;
    const int tx = tid & 15;
    const int ty = tid >> 4;

    float acc[8][8];
    #pragma unroll
    for (int i = 0; i < 8; i++)
        #pragma unroll
        for (int j = 0; j < 8; j++) acc[i][j] = 0.f;

    for (int k0 = 0; k0 < DM_; k0 += 8) {
        float4 av = *(const float4*)(Ap + k0);
        float4 bv = *(const float4*)(Bp + k0);
        __syncthreads();   // previous compute done before overwrite
        As[lc+0][lr] = av.x; As[lc+1][lr] = av.y;
        As[lc+2][lr] = av.z; As[lc+3][lr] = av.w;
        Bs[lc+0][lr] = bv.x; Bs[lc+1][lr] = bv.y;
        Bs[lc+2][lr] = bv.z; Bs[lc+3][lr] = bv.w;
        __syncthreads();
        #pragma unroll
        for (int kk = 0; kk < 8; kk++) {
            float4 a0 = *(const float4*)&As[kk][ty*4];
            float4 a1 = *(const float4*)&As[kk][64 + ty*4];
            float4 b0 = *(const float4*)&Bs[kk][tx*4];
            float4 b1 = *(const float4*)&Bs[kk][64 + tx*4];
            float ar[8] = {a0.x,a0.y,a0.z,a0.w,a1.x,a1.y,a1.z,a1.w};
            float br[8] = {b0.x,b0.y,b0.z,b0.w,b1.x,b1.y,b1.z,b1.w};
            #pragma unroll
            for (int i = 0; i < 8; i++)
                #pragma unroll
                for (int j = 0; j < 8; j++)
                    acc[i][j] += ar[i] * br[j];
        }
    }

    // Epilogue: scatter to [B,H,S,D]
    #pragma unroll
    for (int i = 0; i < 8; i++) {
        int ml = (i < 4) ? (ty*4 + i) : (64 + ty*4 + i - 4);
        int m  = m0 + ml;
        int b  = m >> 11;            // /2048
        int s  = m & (S_ - 1);
        #pragma unroll
        for (int jh = 0; jh < 2; jh++) {
            int nl = jh * 64 + tx*4;
            int n  = n0 + nl;
            int h  = n >> 6;
            int d  = n & 63;
            float4 v = make_float4(acc[i][jh*4+0], acc[i][jh*4+1],
                                   acc[i][jh*4+2], acc[i][jh*4+3]);
            *(float4*)&out[(((size_t)(b*H_ + h))*S_ + s)*D_ + d] = v;
        }
    }
}

// ---------------------------------------------------------------------------
// Kernel 2: RoPE (in-place on g_q/g_k), Q scaled by D^-0.5 = 1/8.
// One thread per (b,h,s,d2) pair, d2 in [0,32).
// ---------------------------------------------------------------------------
__global__ __launch_bounds__(256)
void rope_kernel(const int* __restrict__ pos_ids)
{
    int idx = blockIdx.x * blockDim.x + threadIdx.x;
    const int total = B_ * H_ * S_ * 32;
    if (idx >= total) return;

    int d2 = idx & 31;
    int s  = (idx >> 5)  & (S_ - 1);
    int b  = idx >> 20;                 // 5 + 11 + 4 bits below

    int pos = pos_ids[b * S_ + s];
    // inv_freq = 10000^(-d2/32), computed in double to track jax's fp32 value
    float inv = (float)exp(-(double)d2 * (log(10000.0) / 32.0));
    float ang = (float)pos * inv;
    float sn, cs;
    sincosf(ang, &sn, &cs);

    int base = (idx >> 5) << 6;         // ((b*H+h)*S + s) * 64

    float q1 = g_q[base + d2];
    float q2 = g_q[base + 32 + d2];
    g_q[base + d2]      = 0.125f * (q1 * cs - q2 * sn);
    g_q[base + 32 + d2] = 0.125f * (q2 * cs + q1 * sn);

    float k1 = g_k[base + d2];
    float k2 = g_k[base + 32 + d2];
    g_k[base + d2]      = k1 * cs - k2 * sn;
    g_k[base + 32 + d2] = k2 * cs + k1 * sn;
}

// ---------------------------------------------------------------------------
// Kernel 3: flash attention, 64q x 64k tiles, fp32, online softmax.
// SMEM (dynamic, exactly 48KB): Qs[d][q] 64x64, KP[.]64x64 (K^T, then P^T),
// Vs[k][d] 64x64.
// ---------------------------------------------------------------------------
__global__ __launch_bounds__(256)
void attn_kernel(const float* __restrict__ mask, float* __restrict__ outp)
{
    extern __shared__ float sm[];
    float* Qs = sm;                // [64][64]  (d-major: Qs[d*64 + q])
    float* KP = sm + 64*64;        // [64][64]  Ks[d*64+k], later Ps[k*64+q]
    float* Vs = sm + 2*64*64;      // [64][64]  Vs[k*64+d]

    const int tid = threadIdx.x;
    const int tx  = tid & 15;
    const int ty  = tid >> 4;
    const int b   = blockIdx.z;
    const int h   = blockIdx.y;
    const int q0  = blockIdx.x * 64;

    const float* Qg = g_q + (((size_t)(b*H_ + h))*S_ + q0) * D_;
    const float* Kg = g_k + (((size_t)(b*H_ + h))*S_) * D_;
    const float* Vg = g_v + (((size_t)(b*H_ + h))*S_) * D_;
    const float* Mg = mask + ((size_t)b * S_ + q0) * S_;

    // Load Q tile (transposed to [d][q])
    {
        int r = tid >> 2;                  // 0..63 query row
        #pragma unroll
        for (int it = 0; it < 4; it++) {
            int c4 = (tid & 3) + it * 4;   // float4 index 0..15
            float4 v = *(const float4*)(Qg + r * D_ + c4 * 4);
            int d = c4 * 4;
            Qs[(d+0)*64 + r] = v.x; Qs[(d+1)*64 + r] = v.y;
            Qs[(d+2)*64 + r] = v.z; Qs[(d+3)*64 + r] = v.w;
        }
    }

    float m_i[4], l_i[4], o[4][4];
    #pragma unroll
    for (int i = 0; i < 4; i++) {
        m_i[i] = -1e30f; l_i[i] = 0.f;
        #pragma unroll
        for (int j = 0; j < 4; j++) o[i][j] = 0.f;
    }

    for (int t = 0; t < S_ / 64; t++) {
        const int kbase = t * 64;
        __syncthreads();  // also covers Q-tile stores on t=0, Vs/Ps reuse later

        // Load K tile transposed, V tile straight
        {
            int r = tid >> 2;
            #pragma unroll
            for (int it = 0; it < 4; it++) {
                int c4 = (tid & 3) + it * 4;
                float4 kv = *(const float4*)(Kg + (size_t)(kbase + r) * D_ + c4*4);
                int d = c4 * 4;
                KP[(d+0)*64 + r] = kv.x; KP[(d+1)*64 + r] = kv.y;
                KP[(d+2)*64 + r] = kv.z; KP[(d+3)*64 + r] = kv.w;
                float4 vv = *(const float4*)(Vg + (size_t)(kbase + r) * D_ + c4*4);
                *(float4*)&Vs[r*64 + c4*4] = vv;
            }
        }
        __syncthreads();

        // Scores: acc[i][j] = sum_d Q[q][d] K[k][d]
        float acc[4][4];
        #pragma unroll
        for (int i = 0; i < 4; i++)
            #pragma unroll
            for (int j = 0; j < 4; j++) acc[i][j] = 0.f;

        #pragma unroll 8
        for (int dd = 0; dd < 64; dd++) {
            float4 qv = *(const float4*)&Qs[dd*64 + ty*4];
            float4 kv = *(const float4*)&KP[dd*64 + tx*4];
            float qa[4] = {qv.x, qv.y, qv.z, qv.w};
            float ka[4] = {kv.x, kv.y, kv.z, kv.w};
            #pragma unroll
            for (int i = 0; i < 4; i++)
                #pragma unroll
                for (int j = 0; j < 4; j++)
                    acc[i][j] += qa[i] * ka[j];
        }

        // Add mask + online softmax (rows owned by same-ty 16-lane groups)
        #pragma unroll
        for (int i = 0; i < 4; i++) {
            float4 mv = *(const float4*)(Mg + (size_t)(ty*4 + i) * S_ + kbase + tx*4);
            acc[i][0] += mv.x; acc[i][1] += mv.y;
            acc[i][2] += mv.z; acc[i][3] += mv.w;

            float rmax = fmaxf(fmaxf(acc[i][0], acc[i][1]),
                               fmaxf(acc[i][2], acc[i][3]));
            #pragma unroll
            for (int off = 8; off >= 1; off >>= 1)
                rmax = fmaxf(rmax, __shfl_xor_sync(0xffffffffu, rmax, off, 16));

            float mnew = fmaxf(m_i[i], rmax);
            float rsum = 0.f;
            #pragma unroll
            for (int j = 0; j < 4; j++) {
                acc[i][j] = __expf(acc[i][j] - mnew);
                rsum += acc[i][j];
            }
            #pragma unroll
            for (int off = 8; off >= 1; off >>= 1)
                rsum += __shfl_xor_sync(0xffffffffu, rsum, off, 16);

            float alpha = __expf(m_i[i] - mnew);
            l_i[i] = l_i[i] * alpha + rsum;
            m_i[i] = mnew;
            #pragma unroll
            for (int j = 0; j < 4; j++) o[i][j] *= alpha;
        }

        __syncthreads();   // everyone done reading Ks before P overwrites it

        // Write P transposed: Ps[k][q]
        #pragma unroll
        for (int i = 0; i < 4; i++)
            #pragma unroll
            for (int j = 0; j < 4; j++)
                KP[(tx*4 + j)*64 + (ty*4 + i)] = acc[i][j];
        __syncthreads();

        // o[q][d] += sum_k P[q][k] * V[k][d]
        #pragma unroll 8
        for (int kk = 0; kk < 64; kk++) {
            float4 pv = *(const float4*)&KP[kk*64 + ty*4];
            float4 vv = *(const float4*)&Vs[kk*64 + tx*4];
            float pa[4] = {pv.x, pv.y, pv.z, pv.w};
            float va[4] = {vv.x, vv.y, vv.z, vv.w};
            #pragma unroll
            for (int i = 0; i < 4; i++)
                #pragma unroll
                for (int j = 0; j < 4; j++)
                    o[i][j] += pa[i] * va[j];
        }
    }

    // Normalize and write ctx: out[b][s][h*64 + d]
    #pragma unroll
    for (int i = 0; i < 4; i++) {
        float inv_l = 1.f / l_i[i];
        int q = q0 + ty*4 + i;
        float4 res = make_float4(o[i][0]*inv_l, o[i][1]*inv_l,
                                 o[i][2]*inv_l, o[i][3]*inv_l);
        *(float4*)&outp[((size_t)b * S_ + q) * DM_ + h*64 + tx*4] = res;
    }
}

// ---------------------------------------------------------------------------
extern "C" void kernel_launch(void* const* d_in, const int* in_sizes, int n_in,
                              void* d_out, int out_size)
{
    const float* hidden = (const float*)d_in[0];
    const float* mask   = (const float*)d_in[1];
    const int*   pos    = (const int*)  d_in[2];
    const float* Wq     = (const float*)d_in[3];
    const float* Wk     = (const float*)d_in[4];
    const float* Wv     = (const float*)d_in[5];
    float* out = (float*)d_out;

    dim3 g1(DM_ / 128, (B_ * S_) / 128, 3);
    qkv_gemm<<<g1, 256>>>(hidden, Wq, Wk, Wv);

    int total_pairs = B_ * H_ * S_ * 32;
    rope_kernel<<<(total_pairs + 255) / 256, 256>>>(pos);

    dim3 g2(S_ / 64, H_, B_);
    attn_kernel<<<g2, 256, 3 * 64 * 64 * sizeof(float)>>>(mask, out);
}

// round 6
// speedup vs baseline: 1.0562x; 1.0562x over previous
#include <cuda_runtime.h>
#include <math.h>

#define B_  2
#define S_  2048
#define DM_ 1024
#define H_  16
#define D_  64

// Scratch (allowed: __device__ globals). Layout [B, H, S, D].
__device__ float g_q[B_*H_*S_*D_];
__device__ float g_k[B_*H_*S_*D_];
__device__ float g_v[B_*H_*S_*D_];

// ---------------------------------------------------------------------------
// Kernel 1: P[m,n] = sum_k X[m,k] * W[n,k]   (X: [4096,1024], W: [1024,1024])
// 128x128x8 tile, 256 threads, 8x8 microtile. Output written in [B,H,S,D].
// ---------------------------------------------------------------------------
__global__ __launch_bounds__(256)
void qkv_gemm(const float* __restrict__ X,
              const float* __restrict__ Wq,
              const float* __restrict__ Wk,
              const float* __restrict__ Wv)
{
    __shared__ float As[8][128];   // [k][m]
    __shared__ float Bs[8][128];   // [k][n]

    const float* W;
    float* out;
    if (blockIdx.z == 0)      { W = Wq; out = g_q; }
    else if (blockIdx.z == 1) { W = Wk; out = g_k; }
    else                      { W = Wv; out = g_v; }

    const int tid = threadIdx.x;
    const int m0  = blockIdx.y * 128;
    const int n0  = blockIdx.x * 128;
    const int lr  = tid >> 1;          // 0..127
    const int lc  = (tid & 1) * 4;     // 0 or 4
    const float* Ap = X + (size_t)(m0 + lr) * DM_ + lc;
    const float* Bp = W + (size_t)(n0 + lr) * DM_ + lc;
    const int tx = tid & 15;
    const int ty = tid >> 4;

    float acc[8][8];
    #pragma unroll
    for (int i = 0; i < 8; i++)
        #pragma unroll
        for (int j = 0; j < 8; j++) acc[i][j] = 0.f;

    for (int k0 = 0; k0 < DM_; k0 += 8) {
        float4 av = *(const float4*)(Ap + k0);
        float4 bv = *(const float4*)(Bp + k0);
        __syncthreads();   // previous compute done before overwrite
        As[lc+0][lr] = av.x; As[lc+1][lr] = av.y;
        As[lc+2][lr] = av.z; As[lc+3][lr] = av.w;
        Bs[lc+0][lr] = bv.x; Bs[lc+1][lr] = bv.y;
        Bs[lc+2][lr] = bv.z; Bs[lc+3][lr] = bv.w;
        __syncthreads();
        #pragma unroll
        for (int kk = 0; kk < 8; kk++) {
            float4 a0 = *(const float4*)&As[kk][ty*4];
            float4 a1 = *(const float4*)&As[kk][64 + ty*4];
            float4 b0 = *(const float4*)&Bs[kk][tx*4];
            float4 b1 = *(const float4*)&Bs[kk][64 + tx*4];
            float ar[8] = {a0.x,a0.y,a0.z,a0.w,a1.x,a1.y,a1.z,a1.w};
            float br[8] = {b0.x,b0.y,b0.z,b0.w,b1.x,b1.y,b1.z,b1.w};
            #pragma unroll
            for (int i = 0; i < 8; i++)
                #pragma unroll
                for (int j = 0; j < 8; j++)
                    acc[i][j] += ar[i] * br[j];
        }
    }

    // Epilogue: scatter to [B,H,S,D]
    #pragma unroll
    for (int i = 0; i < 8; i++) {
        int ml = (i < 4) ? (ty*4 + i) : (64 + ty*4 + i - 4);
        int m  = m0 + ml;
        int b  = m >> 11;            // /2048
        int s  = m & (S_ - 1);
        #pragma unroll
        for (int jh = 0; jh < 2; jh++) {
            int nl = jh * 64 + tx*4;
            int n  = n0 + nl;
            int h  = n >> 6;
            int d  = n & 63;
            float4 v = make_float4(acc[i][jh*4+0], acc[i][jh*4+1],
                                   acc[i][jh*4+2], acc[i][jh*4+3]);
            *(float4*)&out[(((size_t)(b*H_ + h))*S_ + s)*D_ + d] = v;
        }
    }
}

// ---------------------------------------------------------------------------
// Kernel 2: RoPE (in-place on g_q/g_k), Q scaled by D^-0.5 = 1/8.
// One thread per (b,h,s,d2) pair, d2 in [0,32).
// ---------------------------------------------------------------------------
__global__ __launch_bounds__(256)
void rope_kernel(const int* __restrict__ pos_ids)
{
    int idx = blockIdx.x * blockDim.x + threadIdx.x;
    const int total = B_ * H_ * S_ * 32;
    if (idx >= total) return;

    int d2 = idx & 31;
    int s  = (idx >> 5)  & (S_ - 1);
    int b  = idx >> 20;                 // 5 + 11 + 4 bits below

    int pos = pos_ids[b * S_ + s];
    // inv_freq = 10000^(-d2/32), computed in double to track jax's fp32 value
    float inv = (float)exp(-(double)d2 * (log(10000.0) / 32.0));
    float ang = (float)pos * inv;
    float sn, cs;
    sincosf(ang, &sn, &cs);

    int base = (idx >> 5) << 6;         // ((b*H+h)*S + s) * 64

    float q1 = g_q[base + d2];
    float q2 = g_q[base + 32 + d2];
    g_q[base + d2]      = 0.125f * (q1 * cs - q2 * sn);
    g_q[base + 32 + d2] = 0.125f * (q2 * cs + q1 * sn);

    float k1 = g_k[base + d2];
    float k2 = g_k[base + 32 + d2];
    g_k[base + d2]      = k1 * cs - k2 * sn;
    g_k[base + 32 + d2] = k2 * cs + k1 * sn;
}

// ---------------------------------------------------------------------------
// Kernel 3: flash attention, 64q x 64k tiles, fp32, online softmax.
// SMEM (dynamic, exactly 48KB): Qs[d][q] 64x64, KP[.]64x64 (K^T, then P^T),
// Vs[k][d] 64x64.
// ---------------------------------------------------------------------------
__global__ __launch_bounds__(256)
void attn_kernel(const float* __restrict__ mask, float* __restrict__ outp)
{
    extern __shared__ float sm[];
    float* Qs = sm;                // [64][64]  (d-major: Qs[d*64 + q])
    float* KP = sm + 64*64;        // [64][64]  Ks[d*64+k], later Ps[k*64+q]
    float* Vs = sm + 2*64*64;      // [64][64]  Vs[k*64+d]

    const int tid = threadIdx.x;
    const int tx  = tid & 15;
    const int ty  = tid >> 4;
    const int b   = blockIdx.z;
    const int h   = blockIdx.y;
    const int q0  = blockIdx.x * 64;

    const float* Qg = g_q + (((size_t)(b*H_ + h))*S_ + q0) * D_;
    const float* Kg = g_k + (((size_t)(b*H_ + h))*S_) * D_;
    const float* Vg = g_v + (((size_t)(b*H_ + h))*S_) * D_;
    const float* Mg = mask + ((size_t)b * S_ + q0) * S_;

    // Load Q tile (transposed to [d][q])
    {
        int r = tid >> 2;                  // 0..63 query row
        #pragma unroll
        for (int it = 0; it < 4; it++) {
            int c4 = (tid & 3) + it * 4;   // float4 index 0..15
            float4 v = *(const float4*)(Qg + r * D_ + c4 * 4);
            int d = c4 * 4;
            Qs[(d+0)*64 + r] = v.x; Qs[(d+1)*64 + r] = v.y;
            Qs[(d+2)*64 + r] = v.z; Qs[(d+3)*64 + r] = v.w;
        }
    }

    float m_i[4], l_i[4], o[4][4];
    #pragma unroll
    for (int i = 0; i < 4; i++) {
        m_i[i] = -1e30f; l_i[i] = 0.f;
        #pragma unroll
        for (int j = 0; j < 4; j++) o[i][j] = 0.f;
    }

    for (int t = 0; t < S_ / 64; t++) {
        const int kbase = t * 64;
        __syncthreads();  // also covers Q-tile stores on t=0, Vs/Ps reuse later

        // Load K tile transposed, V tile straight
        {
            int r = tid >> 2;
            #pragma unroll
            for (int it = 0; it < 4; it++) {
                int c4 = (tid & 3) + it * 4;
                float4 kv = *(const float4*)(Kg + (size_t)(kbase + r) * D_ + c4*4);
                int d = c4 * 4;
                KP[(d+0)*64 + r] = kv.x; KP[(d+1)*64 + r] = kv.y;
                KP[(d+2)*64 + r] = kv.z; KP[(d+3)*64 + r] = kv.w;
                float4 vv = *(const float4*)(Vg + (size_t)(kbase + r) * D_ + c4*4);
                *(float4*)&Vs[r*64 + c4*4] = vv;
            }
        }
        __syncthreads();

        // Scores: acc[i][j] = sum_d Q[q][d] K[k][d]
        float acc[4][4];
        #pragma unroll
        for (int i = 0; i < 4; i++)
            #pragma unroll
            for (int j = 0; j < 4; j++) acc[i][j] = 0.f;

        #pragma unroll 8
        for (int dd = 0; dd < 64; dd++) {
            float4 qv = *(const float4*)&Qs[dd*64 + ty*4];
            float4 kv = *(const float4*)&KP[dd*64 + tx*4];
            float qa[4] = {qv.x, qv.y, qv.z, qv.w};
            float ka[4] = {kv.x, kv.y, kv.z, kv.w};
            #pragma unroll
            for (int i = 0; i < 4; i++)
                #pragma unroll
                for (int j = 0; j < 4; j++)
                    acc[i][j] += qa[i] * ka[j];
        }

        // Add mask + online softmax (rows owned by same-ty 16-lane groups)
        #pragma unroll
        for (int i = 0; i < 4; i++) {
            float4 mv = *(const float4*)(Mg + (size_t)(ty*4 + i) * S_ + kbase + tx*4);
            acc[i][0] += mv.x; acc[i][1] += mv.y;
            acc[i][2] += mv.z; acc[i][3] += mv.w;

            float rmax = fmaxf(fmaxf(acc[i][0], acc[i][1]),
                               fmaxf(acc[i][2], acc[i][3]));
            #pragma unroll
            for (int off = 8; off >= 1; off >>= 1)
                rmax = fmaxf(rmax, __shfl_xor_sync(0xffffffffu, rmax, off, 16));

            float mnew = fmaxf(m_i[i], rmax);
            float rsum = 0.f;
            #pragma unroll
            for (int j = 0; j < 4; j++) {
                acc[i][j] = __expf(acc[i][j] - mnew);
                rsum += acc[i][j];
            }
            #pragma unroll
            for (int off = 8; off >= 1; off >>= 1)
                rsum += __shfl_xor_sync(0xffffffffu, rsum, off, 16);

            float alpha = __expf(m_i[i] - mnew);
            l_i[i] = l_i[i] * alpha + rsum;
            m_i[i] = mnew;
            #pragma unroll
            for (int j = 0; j < 4; j++) o[i][j] *= alpha;
        }

        __syncthreads();   // everyone done reading Ks before P overwrites it

        // Write P transposed: Ps[k][q]
        #pragma unroll
        for (int i = 0; i < 4; i++)
            #pragma unroll
            for (int j = 0; j < 4; j++)
                KP[(tx*4 + j)*64 + (ty*4 + i)] = acc[i][j];
        __syncthreads();

        // o[q][d] += sum_k P[q][k] * V[k][d]
        #pragma unroll 8
        for (int kk = 0; kk < 64; kk++) {
            float4 pv = *(const float4*)&KP[kk*64 + ty*4];
            float4 vv = *(const float4*)&Vs[kk*64 + tx*4];
            float pa[4] = {pv.x, pv.y, pv.z, pv.w};
            float va[4] = {vv.x, vv.y, vv.z, vv.w};
            #pragma unroll
            for (int i = 0; i < 4; i++)
                #pragma unroll
                for (int j = 0; j < 4; j++)
                    o[i][j] += pa[i] * va[j];
        }
    }

    // Normalize and write ctx: out[b][s][h*64 + d]
    #pragma unroll
    for (int i = 0; i < 4; i++) {
        float inv_l = 1.f / l_i[i];
        int q = q0 + ty*4 + i;
        float4 res = make_float4(o[i][0]*inv_l, o[i][1]*inv_l,
                                 o[i][2]*inv_l, o[i][3]*inv_l);
        *(float4*)&outp[((size_t)b * S_ + q) * DM_ + h*64 + tx*4] = res;
    }
}

// ---------------------------------------------------------------------------
extern "C" void kernel_launch(void* const* d_in, const int* in_sizes, int n_in,
                              void* d_out, int out_size)
{
    const float* hidden = (const float*)d_in[0];
    const float* mask   = (const float*)d_in[1];
    const int*   pos    = (const int*)  d_in[2];
    const float* Wq     = (const float*)d_in[3];
    const float* Wk     = (const float*)d_in[4];
    const float* Wv     = (const float*)d_in[5];
    float* out = (float*)d_out;

    dim3 g1(DM_ / 128, (B_ * S_) / 128, 3);
    qkv_gemm<<<g1, 256>>>(hidden, Wq, Wk, Wv);

    int total_pairs = B_ * H_ * S_ * 32;
    rope_kernel<<<(total_pairs + 255) / 256, 256>>>(pos);

    dim3 g2(S_ / 64, H_, B_);
    attn_kernel<<<g2, 256, 3 * 64 * 64 * sizeof(float)>>>(mask, out);
}

// round 7
// speedup vs baseline: 1.0569x; 1.0007x over previous
#include <cuda_runtime.h>
#include <math.h>

#define B_  2
#define S_  2048
#define DM_ 1024
#define H_  16
#define D_  64

// Scratch (allowed: __device__ globals). Layout [B, H, S, D].
__device__ float g_q[B_*H_*S_*D_];
__device__ float g_k[B_*H_*S_*D_];
__device__ float g_v[B_*H_*S_*D_];

// ---------------------------------------------------------------------------
// Kernel 1: P[m,n] = sum_k X[m,k] * W[n,k]   (X: [4096,1024], W: [1024,1024])
// 128x128x8 tile, 256 threads, 8x8 microtile. Output written in [B,H,S,D].
// ---------------------------------------------------------------------------
__global__ __launch_bounds__(256)
void qkv_gemm(const float* __restrict__ X,
              const float* __restrict__ Wq,
              const float* __restrict__ Wk,
              const float* __restrict__ Wv)
{
    __shared__ float As[8][128];   // [k][m]
    __shared__ float Bs[8][128];   // [k][n]

    const float* W;
    float* out;
    if (blockIdx.z == 0)      { W = Wq; out = g_q; }
    else if (blockIdx.z == 1) { W = Wk; out = g_k; }
    else                      { W = Wv; out = g_v; }

    const int tid = threadIdx.x;
    const int m0  = blockIdx.y * 128;
    const int n0  = blockIdx.x * 128;
    const int lr  = tid >> 1;          // 0..127
    const int lc  = (tid & 1) * 4;     // 0 or 4
    const float* Ap = X + (size_t)(m0 + lr) * DM_ + lc;
    const float* Bp = W + (size_t)(n0 + lr) * DM_ + lc;
    const int tx = tid & 15;
    const int ty = tid >> 4;

    float acc[8][8];
    #pragma unroll
    for (int i = 0; i < 8; i++)
        #pragma unroll
        for (int j = 0; j < 8; j++) acc[i][j] = 0.f;

    for (int k0 = 0; k0 < DM_; k0 += 8) {
        float4 av = *(const float4*)(Ap + k0);
        float4 bv = *(const float4*)(Bp + k0);
        __syncthreads();   // previous compute done before overwrite
        As[lc+0][lr] = av.x; As[lc+1][lr] = av.y;
        As[lc+2][lr] = av.z; As[lc+3][lr] = av.w;
        Bs[lc+0][lr] = bv.x; Bs[lc+1][lr] = bv.y;
        Bs[lc+2][lr] = bv.z; Bs[lc+3][lr] = bv.w;
        __syncthreads();
        #pragma unroll
        for (int kk = 0; kk < 8; kk++) {
            float4 a0 = *(const float4*)&As[kk][ty*4];
            float4 a1 = *(const float4*)&As[kk][64 + ty*4];
            float4 b0 = *(const float4*)&Bs[kk][tx*4];
            float4 b1 = *(const float4*)&Bs[kk][64 + tx*4];
            float ar[8] = {a0.x,a0.y,a0.z,a0.w,a1.x,a1.y,a1.z,a1.w};
            float br[8] = {b0.x,b0.y,b0.z,b0.w,b1.x,b1.y,b1.z,b1.w};
            #pragma unroll
            for (int i = 0; i < 8; i++)
                #pragma unroll
                for (int j = 0; j < 8; j++)
                    acc[i][j] += ar[i] * br[j];
        }
    }

    // Epilogue: scatter to [B,H,S,D]
    #pragma unroll
    for (int i = 0; i < 8; i++) {
        int ml = (i < 4) ? (ty*4 + i) : (64 + ty*4 + i - 4);
        int m  = m0 + ml;
        int b  = m >> 11;            // /2048
        int s  = m & (S_ - 1);
        #pragma unroll
        for (int jh = 0; jh < 2; jh++) {
            int nl = jh * 64 + tx*4;
            int n  = n0 + nl;
            int h  = n >> 6;
            int d  = n & 63;
            float4 v = make_float4(acc[i][jh*4+0], acc[i][jh*4+1],
                                   acc[i][jh*4+2], acc[i][jh*4+3]);
            *(float4*)&out[(((size_t)(b*H_ + h))*S_ + s)*D_ + d] = v;
        }
    }
}

// ---------------------------------------------------------------------------
// Kernel 2: RoPE (in-place on g_q/g_k), Q scaled by D^-0.5 = 1/8.
// One thread per (b,h,s,d2) pair, d2 in [0,32).
// ---------------------------------------------------------------------------
__global__ __launch_bounds__(256)
void rope_kernel(const int* __restrict__ pos_ids)
{
    int idx = blockIdx.x * blockDim.x + threadIdx.x;
    const int total = B_ * H_ * S_ * 32;
    if (idx >= total) return;

    int d2 = idx & 31;
    int s  = (idx >> 5)  & (S_ - 1);
    int b  = idx >> 20;                 // 5 + 11 + 4 bits below

    int pos = pos_ids[b * S_ + s];
    // inv_freq = 10000^(-d2/32), computed in double to track jax's fp32 value
    float inv = (float)exp(-(double)d2 * (log(10000.0) / 32.0));
    float ang = (float)pos * inv;
    float sn, cs;
    sincosf(ang, &sn, &cs);

    int base = (idx >> 5) << 6;         // ((b*H+h)*S + s) * 64

    float q1 = g_q[base + d2];
    float q2 = g_q[base + 32 + d2];
    g_q[base + d2]      = 0.125f * (q1 * cs - q2 * sn);
    g_q[base + 32 + d2] = 0.125f * (q2 * cs + q1 * sn);

    float k1 = g_k[base + d2];
    float k2 = g_k[base + 32 + d2];
    g_k[base + d2]      = k1 * cs - k2 * sn;
    g_k[base + 32 + d2] = k2 * cs + k1 * sn;
}

// ---------------------------------------------------------------------------
// Kernel 3: flash attention, 64q x 64k tiles, fp32, online softmax.
// SMEM (dynamic, exactly 48KB): Qs[d][q] 64x64, KP[.]64x64 (K^T, then P^T),
// Vs[k][d] 64x64.
// ---------------------------------------------------------------------------
__global__ __launch_bounds__(256)
void attn_kernel(const float* __restrict__ mask, float* __restrict__ outp)
{
    extern __shared__ float sm[];
    float* Qs = sm;                // [64][64]  (d-major: Qs[d*64 + q])
    float* KP = sm + 64*64;        // [64][64]  Ks[d*64+k], later Ps[k*64+q]
    float* Vs = sm + 2*64*64;      // [64][64]  Vs[k*64+d]

    const int tid = threadIdx.x;
    const int tx  = tid & 15;
    const int ty  = tid >> 4;
    const int b   = blockIdx.z;
    const int h   = blockIdx.y;
    const int q0  = blockIdx.x * 64;

    const float* Qg = g_q + (((size_t)(b*H_ + h))*S_ + q0) * D_;
    const float* Kg = g_k + (((size_t)(b*H_ + h))*S_) * D_;
    const float* Vg = g_v + (((size_t)(b*H_ + h))*S_) * D_;
    const float* Mg = mask + ((size_t)b * S_ + q0) * S_;

    // Load Q tile (transposed to [d][q])
    {
        int r = tid >> 2;                  // 0..63 query row
        #pragma unroll
        for (int it = 0; it < 4; it++) {
            int c4 = (tid & 3) + it * 4;   // float4 index 0..15
            float4 v = *(const float4*)(Qg + r * D_ + c4 * 4);
            int d = c4 * 4;
            Qs[(d+0)*64 + r] = v.x; Qs[(d+1)*64 + r] = v.y;
            Qs[(d+2)*64 + r] = v.z; Qs[(d+3)*64 + r] = v.w;
        }
    }

    float m_i[4], l_i[4], o[4][4];
    #pragma unroll
    for (int i = 0; i < 4; i++) {
        m_i[i] = -1e30f; l_i[i] = 0.f;
        #pragma unroll
        for (int j = 0; j < 4; j++) o[i][j] = 0.f;
    }

    for (int t = 0; t < S_ / 64; t++) {
        const int kbase = t * 64;
        __syncthreads();  // also covers Q-tile stores on t=0, Vs/Ps reuse later

        // Load K tile transposed, V tile straight
        {
            int r = tid >> 2;
            #pragma unroll
            for (int it = 0; it < 4; it++) {
                int c4 = (tid & 3) + it * 4;
                float4 kv = *(const float4*)(Kg + (size_t)(kbase + r) * D_ + c4*4);
                int d = c4 * 4;
                KP[(d+0)*64 + r] = kv.x; KP[(d+1)*64 + r] = kv.y;
                KP[(d+2)*64 + r] = kv.z; KP[(d+3)*64 + r] = kv.w;
                float4 vv = *(const float4*)(Vg + (size_t)(kbase + r) * D_ + c4*4);
                *(float4*)&Vs[r*64 + c4*4] = vv;
            }
        }
        __syncthreads();

        // Scores: acc[i][j] = sum_d Q[q][d] K[k][d]
        float acc[4][4];
        #pragma unroll
        for (int i = 0; i < 4; i++)
            #pragma unroll
            for (int j = 0; j < 4; j++) acc[i][j] = 0.f;

        #pragma unroll 8
        for (int dd = 0; dd < 64; dd++) {
            float4 qv = *(const float4*)&Qs[dd*64 + ty*4];
            float4 kv = *(const float4*)&KP[dd*64 + tx*4];
            float qa[4] = {qv.x, qv.y, qv.z, qv.w};
            float ka[4] = {kv.x, kv.y, kv.z, kv.w};
            #pragma unroll
            for (int i = 0; i < 4; i++)
                #pragma unroll
                for (int j = 0; j < 4; j++)
                    acc[i][j] += qa[i] * ka[j];
        }

        // Add mask + online softmax (rows owned by same-ty 16-lane groups)
        #pragma unroll
        for (int i = 0; i < 4; i++) {
            float4 mv = *(const float4*)(Mg + (size_t)(ty*4 + i) * S_ + kbase + tx*4);
            acc[i][0] += mv.x; acc[i][1] += mv.y;
            acc[i][2] += mv.z; acc[i][3] += mv.w;

            float rmax = fmaxf(fmaxf(acc[i][0], acc[i][1]),
                               fmaxf(acc[i][2], acc[i][3]));
            #pragma unroll
            for (int off = 8; off >= 1; off >>= 1)
                rmax = fmaxf(rmax, __shfl_xor_sync(0xffffffffu, rmax, off, 16));

            float mnew = fmaxf(m_i[i], rmax);
            float rsum = 0.f;
            #pragma unroll
            for (int j = 0; j < 4; j++) {
                acc[i][j] = __expf(acc[i][j] - mnew);
                rsum += acc[i][j];
            }
            #pragma unroll
            for (int off = 8; off >= 1; off >>= 1)
                rsum += __shfl_xor_sync(0xffffffffu, rsum, off, 16);

            float alpha = __expf(m_i[i] - mnew);
            l_i[i] = l_i[i] * alpha + rsum;
            m_i[i] = mnew;
            #pragma unroll
            for (int j = 0; j < 4; j++) o[i][j] *= alpha;
        }

        __syncthreads();   // everyone done reading Ks before P overwrites it

        // Write P transposed: Ps[k][q]
        #pragma unroll
        for (int i = 0; i < 4; i++)
            #pragma unroll
            for (int j = 0; j < 4; j++)
                KP[(tx*4 + j)*64 + (ty*4 + i)] = acc[i][j];
        __syncthreads();

        // o[q][d] += sum_k P[q][k] * V[k][d]
        #pragma unroll 8
        for (int kk = 0; kk < 64; kk++) {
            float4 pv = *(const float4*)&KP[kk*64 + ty*4];
            float4 vv = *(const float4*)&Vs[kk*64 + tx*4];
            float pa[4] = {pv.x, pv.y, pv.z, pv.w};
            float va[4] = {vv.x, vv.y, vv.z, vv.w};
            #pragma unroll
            for (int i = 0; i < 4; i++)
                #pragma unroll
                for (int j = 0; j < 4; j++)
                    o[i][j] += pa[i] * va[j];
        }
    }

    // Normalize and write ctx: out[b][s][h*64 + d]
    #pragma unroll
    for (int i = 0; i < 4; i++) {
        float inv_l = 1.f / l_i[i];
        int q = q0 + ty*4 + i;
        float4 res = make_float4(o[i][0]*inv_l, o[i][1]*inv_l,
                                 o[i][2]*inv_l, o[i][3]*inv_l);
        *(float4*)&outp[((size_t)b * S_ + q) * DM_ + h*64 + tx*4] = res;
    }
}

// ---------------------------------------------------------------------------
extern "C" void kernel_launch(void* const* d_in, const int* in_sizes, int n_in,
                              void* d_out, int out_size)
{
    const float* hidden = (const float*)d_in[0];
    const float* mask   = (const float*)d_in[1];
    const int*   pos    = (const int*)  d_in[2];
    const float* Wq     = (const float*)d_in[3];
    const float* Wk     = (const float*)d_in[4];
    const float* Wv     = (const float*)d_in[5];
    float* out = (float*)d_out;

    dim3 g1(DM_ / 128, (B_ * S_) / 128, 3);
    qkv_gemm<<<g1, 256>>>(hidden, Wq, Wk, Wv);

    int total_pairs = B_ * H_ * S_ * 32;
    rope_kernel<<<(total_pairs + 255) / 256, 256>>>(pos);

    dim3 g2(S_ / 64, H_, B_);
    attn_kernel<<<g2, 256, 3 * 64 * 64 * sizeof(float)>>>(mask, out);
}

// round 8
// speedup vs baseline: 2.0029x; 1.8950x over previous
#include <cuda_runtime.h>
#include <math.h>

#define B_  2
#define S_  2048
#define DM_ 1024
#define H_  16
#define D_  64

// Scratch (allowed: __device__ globals). Layout [B, H, S, D]. fp32.
__device__ float g_q[B_*H_*S_*D_];
__device__ float g_k[B_*H_*S_*D_];
__device__ float g_v[B_*H_*S_*D_];

// --------------------------------------------------------------------------
// tf32 helpers
// --------------------------------------------------------------------------
__device__ __forceinline__ unsigned f2tf(float x) {
    unsigned u;
    asm("cvt.rna.tf32.f32 %0, %1;" : "=r"(u) : "f"(x));
    return u;
}

// D = A(16x8, row) * B(8x8, col) + C   tf32 inputs, fp32 accum
__device__ __forceinline__ void mma_tf32(float d[4], const unsigned a[4],
                                         const unsigned b0, const unsigned b1,
                                         const float c[4]) {
    asm volatile(
        "mma.sync.aligned.m16n8k8.row.col.f32.tf32.tf32.f32 "
        "{%0,%1,%2,%3}, {%4,%5,%6,%7}, {%8,%9}, {%10,%11,%12,%13};"
        : "=f"(d[0]), "=f"(d[1]), "=f"(d[2]), "=f"(d[3])
        : "r"(a[0]), "r"(a[1]), "r"(a[2]), "r"(a[3]),
          "r"(b0), "r"(b1),
          "f"(c[0]), "f"(c[1]), "f"(c[2]), "f"(c[3]));
}

// --------------------------------------------------------------------------
// Kernel 1: P[m,n] = sum_k X[m,k] * W[n,k], tf32 tensor cores.
// Block tile 128x128, k-step 32. 8 warps in 4(m) x 2(n), warp tile 32x64.
// Output scattered to [B,H,S,D].
// --------------------------------------------------------------------------
__global__ __launch_bounds__(256)
void qkv_gemm(const float* __restrict__ X,
              const float* __restrict__ Wq,
              const float* __restrict__ Wk,
              const float* __restrict__ Wv)
{
    __shared__ unsigned As[128][36];   // [m][k], tf32 bits, pad 36 for banks
    __shared__ unsigned Bs[128][36];   // [n][k]

    const float* W;
    float* out;
    if (blockIdx.z == 0)      { W = Wq; out = g_q; }
    else if (blockIdx.z == 1) { W = Wk; out = g_k; }
    else                      { W = Wv; out = g_v; }

    const int tid  = threadIdx.x;
    const int lane = tid & 31;
    const int wid  = tid >> 5;
    const int wm   = wid & 3;        // 0..3 -> m offset wm*32
    const int wn   = wid >> 2;       // 0..1 -> n offset wn*64
    const int g    = lane >> 2;      // group id 0..7
    const int l4   = lane & 3;       // thread in group 0..3

    const int m0 = blockIdx.y * 128;
    const int n0 = blockIdx.x * 128;

    // gmem load mapping: row = tid>>1 (0..127), 4 float4 at cols (tid&1)*16+i*4
    const int lr = tid >> 1;
    const int lc = (tid & 1) * 16;
    const float* Ap = X + (size_t)(m0 + lr) * DM_ + lc;
    const float* Bp = W + (size_t)(n0 + lr) * DM_ + lc;

    float acc[2][8][4];
    #pragma unroll
    for (int mt = 0; mt < 2; mt++)
        #pragma unroll
        for (int nt = 0; nt < 8; nt++)
            #pragma unroll
            for (int i = 0; i < 4; i++) acc[mt][nt][i] = 0.f;

    for (int k0 = 0; k0 < DM_; k0 += 32) {
        float4 av[4], bv[4];
        #pragma unroll
        for (int i = 0; i < 4; i++) {
            av[i] = *(const float4*)(Ap + k0 + i * 4);
            bv[i] = *(const float4*)(Bp + k0 + i * 4);
        }
        __syncthreads();
        #pragma unroll
        for (int i = 0; i < 4; i++) {
            As[lr][lc + i*4 + 0] = f2tf(av[i].x);
            As[lr][lc + i*4 + 1] = f2tf(av[i].y);
            As[lr][lc + i*4 + 2] = f2tf(av[i].z);
            As[lr][lc + i*4 + 3] = f2tf(av[i].w);
            Bs[lr][lc + i*4 + 0] = f2tf(bv[i].x);
            Bs[lr][lc + i*4 + 1] = f2tf(bv[i].y);
            Bs[lr][lc + i*4 + 2] = f2tf(bv[i].z);
            Bs[lr][lc + i*4 + 3] = f2tf(bv[i].w);
        }
        __syncthreads();

        #pragma unroll
        for (int kk = 0; kk < 4; kk++) {
            const int c = kk * 8 + l4;
            unsigned a[2][4];
            #pragma unroll
            for (int mt = 0; mt < 2; mt++) {
                int r = wm * 32 + mt * 16 + g;
                a[mt][0] = As[r][c];
                a[mt][1] = As[r + 8][c];
                a[mt][2] = As[r][c + 4];
                a[mt][3] = As[r + 8][c + 4];
            }
            #pragma unroll
            for (int nt = 0; nt < 8; nt++) {
                int n = wn * 64 + nt * 8 + g;
                unsigned b0 = Bs[n][c];
                unsigned b1 = Bs[n][c + 4];
                mma_tf32(acc[0][nt], a[0], b0, b1, acc[0][nt]);
                mma_tf32(acc[1][nt], a[1], b0, b1, acc[1][nt]);
            }
        }
    }

    // Epilogue: scatter to [B,H,S,D]. C layout: rows g, g+8; cols l4*2, l4*2+1
    #pragma unroll
    for (int mt = 0; mt < 2; mt++) {
        int m = m0 + wm * 32 + mt * 16 + g;
        #pragma unroll
        for (int half = 0; half < 2; half++) {   // half 0: rows g / half 1: g+8
            int mm = m + half * 8;
            int b  = mm >> 11;
            int s  = mm & (S_ - 1);
            #pragma unroll
            for (int nt = 0; nt < 8; nt++) {
                int n = n0 + wn * 64 + nt * 8 + l4 * 2;
                int h = n >> 6;
                int d = n & 63;
                float2 v = make_float2(acc[mt][nt][half*2 + 0],
                                       acc[mt][nt][half*2 + 1]);
                *(float2*)&out[(((size_t)(b*H_ + h))*S_ + s)*D_ + d] = v;
            }
        }
    }
}

// --------------------------------------------------------------------------
// Kernel 2: RoPE (in-place on g_q/g_k), Q scaled by D^-0.5 = 1/8.
// --------------------------------------------------------------------------
__global__ __launch_bounds__(256)
void rope_kernel(const int* __restrict__ pos_ids)
{
    int idx = blockIdx.x * blockDim.x + threadIdx.x;
    const int total = B_ * H_ * S_ * 32;
    if (idx >= total) return;

    int d2 = idx & 31;
    int s  = (idx >> 5)  & (S_ - 1);
    int b  = idx >> 20;

    int pos = pos_ids[b * S_ + s];
    float inv = (float)exp(-(double)d2 * (log(10000.0) / 32.0));
    float ang = (float)pos * inv;
    float sn, cs;
    sincosf(ang, &sn, &cs);

    int base = (idx >> 5) << 6;

    float q1 = g_q[base + d2];
    float q2 = g_q[base + 32 + d2];
    g_q[base + d2]      = 0.125f * (q1 * cs - q2 * sn);
    g_q[base + 32 + d2] = 0.125f * (q2 * cs + q1 * sn);

    float k1 = g_k[base + d2];
    float k2 = g_k[base + 32 + d2];
    g_k[base + d2]      = k1 * cs - k2 * sn;
    g_k[base + 32 + d2] = k2 * cs + k1 * sn;
}

// --------------------------------------------------------------------------
// Kernel 3: flash attention with tf32 tensor cores.
// Block = 128 threads (4 warps). Q tile 64 rows (16 per warp), K tile 64.
// Ks[kpos][d] : B operand for S = Q K^T.  Vt[d][kpos]: B operand for PV.
// P stays in registers: C-fragment -> A-fragment via quad shuffles.
// --------------------------------------------------------------------------
__global__ __launch_bounds__(128)
void attn_tf32(const float* __restrict__ mask, float* __restrict__ outp)
{
    __shared__ unsigned Ks[64][68];
    __shared__ unsigned Vt[64][68];

    const int tid  = threadIdx.x;
    const int lane = tid & 31;
    const int wid  = tid >> 5;     // 0..3
    const int g    = lane >> 2;    // 0..7
    const int l4   = lane & 3;     // 0..3

    const int b  = blockIdx.z;
    const int h  = blockIdx.y;
    const int q0 = blockIdx.x * 64;

    const float* Qg = g_q + (((size_t)(b*H_ + h))*S_ + q0) * D_;
    const float* Kg = g_k + (((size_t)(b*H_ + h))*S_) * D_;
    const float* Vg = g_v + (((size_t)(b*H_ + h))*S_) * D_;
    const float* Mg = mask + ((size_t)b * S_ + q0) * S_;

    const int r0 = wid * 16 + g;   // this thread's first q-row (local)

    // Q A-fragments, loaded once (tf32). qa[kk] covers d = kk*8..kk*8+7.
    unsigned qa[8][4];
    #pragma unroll
    for (int kk = 0; kk < 8; kk++) {
        qa[kk][0] = f2tf(Qg[(size_t)r0       * D_ + kk*8 + l4]);
        qa[kk][1] = f2tf(Qg[(size_t)(r0 + 8) * D_ + kk*8 + l4]);
        qa[kk][2] = f2tf(Qg[(size_t)r0       * D_ + kk*8 + l4 + 4]);
        qa[kk][3] = f2tf(Qg[(size_t)(r0 + 8) * D_ + kk*8 + l4 + 4]);
    }

    float o[8][4];
    #pragma unroll
    for (int nt = 0; nt < 8; nt++)
        #pragma unroll
        for (int i = 0; i < 4; i++) o[nt][i] = 0.f;
    float m0r = -1e30f, m1r = -1e30f, l0r = 0.f, l1r = 0.f;

    // K/V gmem load mapping: kr = tid&63 (row), half = tid>>6 (d half)
    const int kr   = tid & 63;
    const int half = tid >> 6;

    for (int t = 0; t < S_ / 64; t++) {
        const int kbase = t * 64;
        __syncthreads();
        {
            const float* Kp = Kg + (size_t)(kbase + kr) * D_ + half * 32;
            const float* Vp = Vg + (size_t)(kbase + kr) * D_ + half * 32;
            #pragma unroll
            for (int i = 0; i < 8; i++) {
                float4 kv = *(const float4*)(Kp + i * 4);
                uint4 kt;
                kt.x = f2tf(kv.x); kt.y = f2tf(kv.y);
                kt.z = f2tf(kv.z); kt.w = f2tf(kv.w);
                *(uint4*)&Ks[kr][half*32 + i*4] = kt;

                float4 vv = *(const float4*)(Vp + i * 4);
                int d = half*32 + i*4;
                Vt[d + 0][kr] = f2tf(vv.x);
                Vt[d + 1][kr] = f2tf(vv.y);
                Vt[d + 2][kr] = f2tf(vv.z);
                Vt[d + 3][kr] = f2tf(vv.w);
            }
        }
        __syncthreads();

        // ---- S = Q K^T  (s[nt] covers kpos nt*8..nt*8+7) ----
        float s[8][4];
        #pragma unroll
        for (int nt = 0; nt < 8; nt++)
            #pragma unroll
            for (int i = 0; i < 4; i++) s[nt][i] = 0.f;

        #pragma unroll
        for (int kk = 0; kk < 8; kk++) {
            const int c = kk * 8 + l4;
            #pragma unroll
            for (int nt = 0; nt < 8; nt++) {
                unsigned b0 = Ks[nt*8 + g][c];
                unsigned b1 = Ks[nt*8 + g][c + 4];
                mma_tf32(s[nt], qa[kk], b0, b1, s[nt]);
            }
        }

        // ---- mask add (fragment-layout float2 loads) ----
        #pragma unroll
        for (int nt = 0; nt < 8; nt++) {
            const float* mp = Mg + (size_t)r0 * S_ + kbase + nt*8 + l4*2;
            float2 ma = *(const float2*)mp;
            float2 mb = *(const float2*)(mp + 8 * S_);
            s[nt][0] += ma.x; s[nt][1] += ma.y;
            s[nt][2] += mb.x; s[nt][3] += mb.y;
        }

        // ---- online softmax (rows r0 and r0+8) ----
        float mx0 = -1e30f, mx1 = -1e30f;
        #pragma unroll
        for (int nt = 0; nt < 8; nt++) {
            mx0 = fmaxf(mx0, fmaxf(s[nt][0], s[nt][1]));
            mx1 = fmaxf(mx1, fmaxf(s[nt][2], s[nt][3]));
        }
        mx0 = fmaxf(mx0, __shfl_xor_sync(0xffffffffu, mx0, 1));
        mx0 = fmaxf(mx0, __shfl_xor_sync(0xffffffffu, mx0, 2));
        mx1 = fmaxf(mx1, __shfl_xor_sync(0xffffffffu, mx1, 1));
        mx1 = fmaxf(mx1, __shfl_xor_sync(0xffffffffu, mx1, 2));

        float mn0 = fmaxf(m0r, mx0);
        float mn1 = fmaxf(m1r, mx1);

        float sum0 = 0.f, sum1 = 0.f;
        #pragma unroll
        for (int nt = 0; nt < 8; nt++) {
            s[nt][0] = __expf(s[nt][0] - mn0);
            s[nt][1] = __expf(s[nt][1] - mn0);
            s[nt][2] = __expf(s[nt][2] - mn1);
            s[nt][3] = __expf(s[nt][3] - mn1);
            sum0 += s[nt][0] + s[nt][1];
            sum1 += s[nt][2] + s[nt][3];
        }
        sum0 += __shfl_xor_sync(0xffffffffu, sum0, 1);
        sum0 += __shfl_xor_sync(0xffffffffu, sum0, 2);
        sum1 += __shfl_xor_sync(0xffffffffu, sum1, 1);
        sum1 += __shfl_xor_sync(0xffffffffu, sum1, 2);

        float a0 = __expf(m0r - mn0);
        float a1 = __expf(m1r - mn1);
        l0r = l0r * a0 + sum0;
        l1r = l1r * a1 + sum1;
        m0r = mn0; m1r = mn1;
        #pragma unroll
        for (int nt = 0; nt < 8; nt++) {
            o[nt][0] *= a0; o[nt][1] *= a0;
            o[nt][2] *= a1; o[nt][3] *= a1;
        }

        // ---- PV: o += P * V.  P C-frag -> A-frag via quad shuffles ----
        const int src  = (lane & ~3) | (l4 >> 1);
        const int src2 = src + 2;
        const bool odd = (l4 & 1);
        #pragma unroll
        for (int kk = 0; kk < 8; kk++) {
            float v00 = __shfl_sync(0xffffffffu, s[kk][0], src);
            float v01 = __shfl_sync(0xffffffffu, s[kk][1], src);
            float v10 = __shfl_sync(0xffffffffu, s[kk][2], src);
            float v11 = __shfl_sync(0xffffffffu, s[kk][3], src);
            float w00 = __shfl_sync(0xffffffffu, s[kk][0], src2);
            float w01 = __shfl_sync(0xffffffffu, s[kk][1], src2);
            float w10 = __shfl_sync(0xffffffffu, s[kk][2], src2);
            float w11 = __shfl_sync(0xffffffffu, s[kk][3], src2);
            unsigned pa[4];
            pa[0] = f2tf(odd ? v01 : v00);   // (row g,   k=l4)
            pa[1] = f2tf(odd ? v11 : v10);   // (row g+8, k=l4)
            pa[2] = f2tf(odd ? w01 : w00);   // (row g,   k=l4+4)
            pa[3] = f2tf(odd ? w11 : w10);   // (row g+8, k=l4+4)

            const int c = kk * 8 + l4;
            #pragma unroll
            for (int nt = 0; nt < 8; nt++) {
                unsigned b0 = Vt[nt*8 + g][c];
                unsigned b1 = Vt[nt*8 + g][c + 4];
                mma_tf32(o[nt], pa, b0, b1, o[nt]);
            }
        }
    }

    // ---- normalize + write ctx: out[b][s][h*64 + d] ----
    float inv0 = 1.f / l0r;
    float inv1 = 1.f / l1r;
    #pragma unroll
    for (int nt = 0; nt < 8; nt++) {
        int d = h * 64 + nt * 8 + l4 * 2;
        float2 r0v = make_float2(o[nt][0] * inv0, o[nt][1] * inv0);
        float2 r1v = make_float2(o[nt][2] * inv1, o[nt][3] * inv1);
        *(float2*)&outp[((size_t)b * S_ + q0 + r0    ) * DM_ + d] = r0v;
        *(float2*)&outp[((size_t)b * S_ + q0 + r0 + 8) * DM_ + d] = r1v;
    }
}

// --------------------------------------------------------------------------
extern "C" void kernel_launch(void* const* d_in, const int* in_sizes, int n_in,
                              void* d_out, int out_size)
{
    const float* hidden = (const float*)d_in[0];
    const float* mask   = (const float*)d_in[1];
    const int*   pos    = (const int*)  d_in[2];
    const float* Wq     = (const float*)d_in[3];
    const float* Wk     = (const float*)d_in[4];
    const float* Wv     = (const float*)d_in[5];
    float* out = (float*)d_out;

    dim3 g1(DM_ / 128, (B_ * S_) / 128, 3);
    qkv_gemm<<<g1, 256>>>(hidden, Wq, Wk, Wv);

    int total_pairs = B_ * H_ * S_ * 32;
    rope_kernel<<<(total_pairs + 255) / 256, 256>>>(pos);

    dim3 g2(S_ / 64, H_, B_);
    attn_tf32<<<g2, 128>>>(mask, out);
}